// round 4
// baseline (speedup 1.0000x reference)
#include <cuda_runtime.h>
#include <math.h>

// Problem constants (fixed shapes: kernels [1,8192,256] f32, categories [1,8192] i32, scores [1,8192] f32)
#define NN   8192
#define DD   256
#define D4   64          // DD/4
#define NC   128         // category slots (actual range 0..79)
#define TS   32          // member tile size for pair kernel
#define PITCH4 65        // float4 row pitch in smem (64 + 1 pad -> conflict-free column access)
#define THRESH 0.95f
#define EPSN 1e-8f

// Output layout: ALL float32, concatenated (harness packs outputs in one dtype):
//   fused  [NN*DD] @ element 0
//   cats   [NN]    @ element NN*DD      (float value; -1.0 for dropped)
//   scores [NN]    @ element NN*DD+NN
//   keep   [NN]    @ element NN*DD+2*NN (1.0 / 0.0)

// ---------------- device scratch (static, allocation-free) ----------------
__device__ float g_invn[NN];
__device__ int   g_cnt[NC];
__device__ int   g_off[NC];
__device__ int   g_fill[NC];
__device__ int   g_members[NN];
__device__ int   g_tpoff[NC + 1];
__device__ int   g_total;
__device__ int   g_ctr;
__device__ int   g_claim[NN];
__device__ int   g_cnt2[NN];

static __device__ __forceinline__ int clamp_cat(int ci) {
    if (ci < 0) ci = 0;
    if (ci > NC - 1) ci = NC - 1;
    return ci;
}

// ---------------- K0: zero counters ----------------
__global__ void k_zero() {
    int t = threadIdx.x;
    if (t < NC) { g_cnt[t] = 0; g_fill[t] = 0; }
    if (t == 0) g_ctr = 0;
}

// ---------------- K1: per-row inverse norm + histogram + claim init ----------------
__global__ void k_norm(const float* __restrict__ kin, const int* __restrict__ cat) {
    int row = blockIdx.x;
    int t = threadIdx.x;
    float v = kin[row * DD + t];
    float s = v * v;
    __shared__ float red[8];
    #pragma unroll
    for (int o = 16; o; o >>= 1) s += __shfl_xor_sync(0xFFFFFFFFu, s, o);
    if ((t & 31) == 0) red[t >> 5] = s;
    __syncthreads();
    if (t < 8) {
        float x = red[t];
        #pragma unroll
        for (int o = 4; o; o >>= 1) x += __shfl_xor_sync(0xFFu, x, o);
        if (t == 0) {
            float nrm = fmaxf(sqrtf(x), EPSN);
            g_invn[row] = 1.0f / nrm;
            g_claim[row] = row;
            g_cnt2[row] = 0;
            atomicAdd(&g_cnt[clamp_cat(cat[row])], 1);
        }
    }
}

// ---------------- K2: serial scan over 128 categories (tiny) ----------------
__global__ void k_scan() {
    if (threadIdx.x != 0 || blockIdx.x != 0) return;
    int acc = 0, tacc = 0;
    for (int c = 0; c < NC; c++) {
        g_off[c] = acc;
        acc += g_cnt[c];
        g_tpoff[c] = tacc;
        int T = (g_cnt[c] + TS - 1) / TS;
        tacc += T * (T + 1) / 2;
    }
    g_tpoff[NC] = tacc;
    g_total = tacc;
    g_ctr = 0;
}

// ---------------- K3: scatter member lists (order irrelevant: we min by index) ----------------
__global__ void k_scatter(const int* __restrict__ cat) {
    int idx = blockIdx.x * blockDim.x + threadIdx.x;
    if (idx >= NN) return;
    int ci = clamp_cat(cat[idx]);
    int pos = g_off[ci] + atomicAdd(&g_fill[ci], 1);
    g_members[pos] = idx;
}

// ---------------- K4: persistent pair kernel ----------------
// Work item = (category, tileA, tileB) with tileA <= tileB, tiles of TS members.
// Stage both tiles (normalized rows) in padded shared memory; each thread computes 4 dots.
// On hit (same cat implied, different rows, dot >= THRESH): atomicMin(claim[max], min).
__global__ void __launch_bounds__(256, 3) k_pairs(const float* __restrict__ kin) {
    extern __shared__ float4 sm[];
    float4* sA = sm;                  // TS * PITCH4
    float4* sB = sm + TS * PITCH4;    // TS * PITCH4
    __shared__ int gA[TS], gB[TS];
    __shared__ int s_w, s_ta, s_tb, s_base, s_na, s_nb;

    const float4* k4g = (const float4*)kin;
    const int t = threadIdx.x;

    for (;;) {
        if (t == 0) {
            int w = atomicAdd(&g_ctr, 1);
            s_w = w;
            if (w < g_total) {
                int c = 0;
                while (w >= g_tpoff[c + 1]) c++;
                int p = w - g_tpoff[c];
                int cc = g_cnt[c];
                int T = (cc + TS - 1) / TS;
                int ta = 0;
                while (p >= T - ta) { p -= T - ta; ta++; }
                s_ta = ta;
                s_tb = ta + p;
                s_base = g_off[c];
                s_na = min(TS, cc - ta * TS);
                s_nb = min(TS, cc - (ta + p) * TS);
            }
        }
        __syncthreads();                       // also fences prior iteration's smem reads
        if (s_w >= g_total) break;
        int na = s_na, nb = s_nb, base = s_base, ta = s_ta, tb = s_tb;

        if (t < TS) {
            gA[t] = (t < na) ? g_members[base + ta * TS + t] : -1;
            gB[t] = (t < nb) ? g_members[base + tb * TS + t] : -1;
        }
        __syncthreads();

        // stage normalized rows
        for (int i = t; i < TS * D4; i += 256) {
            int r = i >> 6, k4 = i & 63;
            float4 va = make_float4(0.f, 0.f, 0.f, 0.f);
            int g = gA[r];
            if (g >= 0) {
                va = k4g[g * D4 + k4];
                float sc = g_invn[g];
                va.x *= sc; va.y *= sc; va.z *= sc; va.w *= sc;
            }
            sA[r * PITCH4 + k4] = va;
            float4 vb = make_float4(0.f, 0.f, 0.f, 0.f);
            g = gB[r];
            if (g >= 0) {
                vb = k4g[g * D4 + k4];
                float sc = g_invn[g];
                vb.x *= sc; vb.y *= sc; vb.z *= sc; vb.w *= sc;
            }
            sB[r * PITCH4 + k4] = vb;
        }
        __syncthreads();

        int ra = t & 31;     // varies within warp -> conflict-free strided sA reads
        int rq = t >> 5;     // constant within warp -> broadcast sB reads
        float a0 = 0.f, a1 = 0.f, a2 = 0.f, a3 = 0.f;
        #pragma unroll 4
        for (int k4 = 0; k4 < D4; k4++) {
            float4 a  = sA[ra * PITCH4 + k4];
            float4 b0 = sB[(rq      ) * PITCH4 + k4];
            float4 b1 = sB[(rq +  8 ) * PITCH4 + k4];
            float4 b2 = sB[(rq + 16 ) * PITCH4 + k4];
            float4 b3 = sB[(rq + 24 ) * PITCH4 + k4];
            a0 += a.x * b0.x + a.y * b0.y + a.z * b0.z + a.w * b0.w;
            a1 += a.x * b1.x + a.y * b1.y + a.z * b1.z + a.w * b1.w;
            a2 += a.x * b2.x + a.y * b2.y + a.z * b2.z + a.w * b2.w;
            a3 += a.x * b3.x + a.y * b3.y + a.z * b3.z + a.w * b3.w;
        }
        if (ra < na) {
            int ga = gA[ra];
            float accs[4] = {a0, a1, a2, a3};
            #pragma unroll
            for (int j = 0; j < 4; j++) {
                int rb = rq + 8 * j;
                if (rb < nb) {
                    int gb = gB[rb];
                    if (gb != ga && accs[j] >= THRESH) {
                        int lo = min(ga, gb), hi = max(ga, gb);
                        atomicMin(&g_claim[hi], lo);
                    }
                }
            }
        }
    }
}

// ---------------- K5: zero fused region + claim counts + tail outputs (all float32) ----------------
__global__ void k_mid(float* __restrict__ out,
                      const int* __restrict__ cat,
                      const float* __restrict__ scores) {
    int stride = gridDim.x * blockDim.x;
    for (int idx = blockIdx.x * blockDim.x + threadIdx.x; idx < NN * DD; idx += stride) {
        out[idx] = 0.0f;
        if (idx < NN) {
            int i = g_claim[idx];
            if (g_claim[i] == i) atomicAdd(&g_cnt2[i], 1);
            bool keep = (i == idx);
            out[NN * DD + idx]          = keep ? (float)cat[idx] : -1.0f;
            out[NN * DD + NN + idx]     = keep ? scores[idx] : 0.0f;
            out[NN * DD + 2 * NN + idx] = keep ? 1.0f : 0.0f;
        }
    }
}

// ---------------- K6: fused scatter ----------------
__global__ void k_fused(float* __restrict__ out, const float* __restrict__ kin) {
    int j = blockIdx.x;
    int t = threadIdx.x;           // 64 threads, one float4 each
    int i = g_claim[j];
    if (g_claim[i] != i) return;   // owner dropped -> contributes nothing (row stays 0)
    int n = g_cnt2[i];
    const float4* k4g = (const float4*)kin;
    float4 v = k4g[j * D4 + t];
    if (n == 1) {
        // unique member of its cluster is the owner itself (j == i): exact copy
        ((float4*)out)[i * D4 + t] = v;
    } else {
        float w = 1.0f / (float)n;
        atomicAdd(&out[i * DD + t * 4 + 0], v.x * w);
        atomicAdd(&out[i * DD + t * 4 + 1], v.y * w);
        atomicAdd(&out[i * DD + t * 4 + 2], v.z * w);
        atomicAdd(&out[i * DD + t * 4 + 3], v.w * w);
    }
}

// ---------------- launch ----------------
extern "C" void kernel_launch(void* const* d_in, const int* in_sizes, int n_in,
                              void* d_out, int out_size) {
    const float* kin    = (const float*)d_in[0];
    const int*   cat    = (const int*)d_in[1];
    const float* scores = (const float*)d_in[2];
    float*       out    = (float*)d_out;

    (void)in_sizes; (void)n_in; (void)out_size;

    const int smem = 2 * TS * PITCH4 * (int)sizeof(float4);  // 66,560 B
    cudaFuncSetAttribute(k_pairs, cudaFuncAttributeMaxDynamicSharedMemorySize, smem);

    k_zero<<<1, 256>>>();
    k_norm<<<NN, 256>>>(kin, cat);
    k_scan<<<1, 32>>>();
    k_scatter<<<(NN + 255) / 256, 256>>>(cat);
    k_pairs<<<444, 256, smem>>>(kin);
    k_mid<<<2048, 256>>>(out, cat, scores);
    k_fused<<<NN, 64>>>(out, kin);
}

// round 5
// speedup vs baseline: 1.0685x; 1.0685x over previous
#include <cuda_runtime.h>
#include <math.h>

// Fixed shapes: kernels [1,8192,256] f32, categories [1,8192] i32, scores [1,8192] f32
#define NN   8192
#define DD   256
#define D4   64          // DD/4
#define NC   128         // category slots (actual range 0..79)
#define TS   32          // member tile size for pair kernel
#define PITCH4 65        // float4 row pitch in smem (64 + 1 pad -> conflict-free column access)
#define THRESH 0.95f
#define EPSN 1e-8f

// Output: ALL float32, concatenated:
//   fused [NN*DD] @0, cats [NN] @NN*DD, scores [NN] @NN*DD+NN, keep [NN] @NN*DD+2*NN

// ---------------- device scratch ----------------
// Invariant: g_cnt[] and g_ctr are ZERO at kernel_launch entry. They start zero
// (static init) and are re-zeroed at the end of every run (k_prep / k_finalize),
// so graph replays are deterministic.
__device__ float g_invn[NN];
__device__ int   g_cnt[NC];
__device__ int   g_off[NC];
__device__ int   g_tpoff[NC + 1];
__device__ int   g_total;
__device__ int   g_ctr;
__device__ int   g_members[NN];
__device__ int   g_claim[NN];
__device__ int   g_cnt2[NN];

static __device__ __forceinline__ int clamp_cat(int ci) {
    if (ci < 0) ci = 0;
    if (ci > NC - 1) ci = NC - 1;
    return ci;
}

// ---------------- K1: warp-per-row inverse norm + histogram + claim init ----------------
__global__ void __launch_bounds__(256) k_norm(const float* __restrict__ kin,
                                              const int* __restrict__ cat) {
    int w = threadIdx.x >> 5, lane = threadIdx.x & 31;
    int row = blockIdx.x * 8 + w;
    const float4* k4 = (const float4*)kin;
    float4 a = k4[row * D4 + lane];
    float4 b = k4[row * D4 + 32 + lane];
    float s = a.x * a.x + a.y * a.y + a.z * a.z + a.w * a.w
            + b.x * b.x + b.y * b.y + b.z * b.z + b.w * b.w;
    #pragma unroll
    for (int o = 16; o; o >>= 1) s += __shfl_xor_sync(0xFFFFFFFFu, s, o);
    if (lane == 0) {
        g_invn[row]  = 1.0f / fmaxf(sqrtf(s), EPSN);
        g_claim[row] = row;
        g_cnt2[row]  = 0;
        atomicAdd(&g_cnt[clamp_cat(cat[row])], 1);
    }
}

// ---------------- K2: single-block scan + scatter (smem fill counters) ----------------
__global__ void __launch_bounds__(256) k_build(const int* __restrict__ cat) {
    __shared__ int sfill[NC];
    int t = threadIdx.x;
    if (t == 0) {
        int acc = 0, tacc = 0;
        #pragma unroll 4
        for (int c = 0; c < NC; c++) {
            g_off[c] = acc;
            sfill[c] = acc;          // visible after syncthreads; sfill[c] init here
            acc += g_cnt[c];
            g_tpoff[c] = tacc;
            int T = (g_cnt[c] + TS - 1) / TS;
            tacc += T * (T + 1) / 2;
        }
        g_tpoff[NC] = tacc;
        g_total = tacc;
    }
    __syncthreads();
    for (int idx = t; idx < NN; idx += 256) {
        int ci = clamp_cat(cat[idx]);
        int pos = atomicAdd(&sfill[ci], 1);
        g_members[pos] = idx;
    }
}

// ---------------- K3: persistent pair kernel (unchanged core) ----------------
__global__ void __launch_bounds__(256, 3) k_pairs(const float* __restrict__ kin) {
    extern __shared__ float4 sm[];
    float4* sA = sm;
    float4* sB = sm + TS * PITCH4;
    __shared__ int gA[TS], gB[TS];
    __shared__ int s_w, s_ta, s_tb, s_base, s_na, s_nb;

    const float4* k4g = (const float4*)kin;
    const int t = threadIdx.x;

    for (;;) {
        if (t == 0) {
            int w = atomicAdd(&g_ctr, 1);
            s_w = w;
            if (w < g_total) {
                int c = 0;
                while (w >= g_tpoff[c + 1]) c++;
                int p = w - g_tpoff[c];
                int cc = g_cnt[c];
                int T = (cc + TS - 1) / TS;
                int ta = 0;
                while (p >= T - ta) { p -= T - ta; ta++; }
                s_ta = ta;
                s_tb = ta + p;
                s_base = g_off[c];
                s_na = min(TS, cc - ta * TS);
                s_nb = min(TS, cc - (ta + p) * TS);
            }
        }
        __syncthreads();
        if (s_w >= g_total) break;
        int na = s_na, nb = s_nb, base = s_base, ta = s_ta, tb = s_tb;

        if (t < TS) {
            gA[t] = (t < na) ? g_members[base + ta * TS + t] : -1;
            gB[t] = (t < nb) ? g_members[base + tb * TS + t] : -1;
        }
        __syncthreads();

        for (int i = t; i < TS * D4; i += 256) {
            int r = i >> 6, k4 = i & 63;
            float4 va = make_float4(0.f, 0.f, 0.f, 0.f);
            int g = gA[r];
            if (g >= 0) {
                va = k4g[g * D4 + k4];
                float sc = g_invn[g];
                va.x *= sc; va.y *= sc; va.z *= sc; va.w *= sc;
            }
            sA[r * PITCH4 + k4] = va;
            float4 vb = make_float4(0.f, 0.f, 0.f, 0.f);
            g = gB[r];
            if (g >= 0) {
                vb = k4g[g * D4 + k4];
                float sc = g_invn[g];
                vb.x *= sc; vb.y *= sc; vb.z *= sc; vb.w *= sc;
            }
            sB[r * PITCH4 + k4] = vb;
        }
        __syncthreads();

        int ra = t & 31;
        int rq = t >> 5;
        float a0 = 0.f, a1 = 0.f, a2 = 0.f, a3 = 0.f;
        #pragma unroll 4
        for (int k4 = 0; k4 < D4; k4++) {
            float4 a  = sA[ra * PITCH4 + k4];
            float4 b0 = sB[(rq      ) * PITCH4 + k4];
            float4 b1 = sB[(rq +  8 ) * PITCH4 + k4];
            float4 b2 = sB[(rq + 16 ) * PITCH4 + k4];
            float4 b3 = sB[(rq + 24 ) * PITCH4 + k4];
            a0 += a.x * b0.x + a.y * b0.y + a.z * b0.z + a.w * b0.w;
            a1 += a.x * b1.x + a.y * b1.y + a.z * b1.z + a.w * b1.w;
            a2 += a.x * b2.x + a.y * b2.y + a.z * b2.z + a.w * b2.w;
            a3 += a.x * b3.x + a.y * b3.y + a.z * b3.z + a.w * b3.w;
        }
        if (ra < na) {
            int ga = gA[ra];
            float accs[4] = {a0, a1, a2, a3};
            #pragma unroll
            for (int j = 0; j < 4; j++) {
                int rb = rq + 8 * j;
                if (rb < nb) {
                    int gb = gB[rb];
                    if (gb != ga && accs[j] >= THRESH) {
                        int lo = min(ga, gb), hi = max(ga, gb);
                        atomicMin(&g_claim[hi], lo);
                    }
                }
            }
        }
    }
}

// ---------------- K4: prep — tail outputs, cluster counts, sparse zeroing ----------------
// Zeroes ONLY rows that need it: dropped rows and multi-member cluster owner rows.
__global__ void __launch_bounds__(256) k_prep(float* __restrict__ out,
                                              const int* __restrict__ cat,
                                              const float* __restrict__ scores) {
    int idx = blockIdx.x * 256 + threadIdx.x;
    int c = g_claim[idx];
    bool keep = (c == idx);
    out[NN * DD + idx]          = keep ? (float)cat[idx] : -1.0f;
    out[NN * DD + NN + idx]     = keep ? scores[idx] : 0.0f;
    out[NN * DD + 2 * NN + idx] = keep ? 1.0f : 0.0f;

    bool owner_kept = (g_claim[c] == c);
    if (owner_kept) atomicAdd(&g_cnt2[c], 1);   // distinct addresses in common case

    if (!keep) {
        float4 z = make_float4(0.f, 0.f, 0.f, 0.f);
        float4* o4 = (float4*)out;
        #pragma unroll 4
        for (int k = 0; k < D4; k++) o4[idx * D4 + k] = z;   // dropped row -> zeros
        if (owner_kept) {
            #pragma unroll 4
            for (int k = 0; k < D4; k++) o4[c * D4 + k] = z; // owner row will be accumulated
        }
    }
    if (idx == 0) g_ctr = 0;   // restore invariant for next replay
}

// ---------------- K5: finalize — copy/accumulate fused rows, reset counters ----------------
__global__ void __launch_bounds__(256) k_finalize(float* __restrict__ out,
                                                  const float* __restrict__ kin) {
    int j = blockIdx.x * 4 + (threadIdx.x >> 6);
    int t = threadIdx.x & 63;
    int i = g_claim[j];
    if (g_claim[i] == i) {
        const float4* k4g = (const float4*)kin;
        float4 v = k4g[j * D4 + t];
        int n = g_cnt2[i];
        if (n == 1) {
            ((float4*)out)[i * D4 + t] = v;   // singleton: exact copy (j == i)
        } else {
            float w = 1.0f / (float)n;
            atomicAdd(&out[i * DD + t * 4 + 0], v.x * w);
            atomicAdd(&out[i * DD + t * 4 + 1], v.y * w);
            atomicAdd(&out[i * DD + t * 4 + 2], v.z * w);
            atomicAdd(&out[i * DD + t * 4 + 3], v.w * w);
        }
    }
    if (blockIdx.x == 0 && threadIdx.x < NC) g_cnt[threadIdx.x] = 0;  // restore invariant
}

// ---------------- launch ----------------
extern "C" void kernel_launch(void* const* d_in, const int* in_sizes, int n_in,
                              void* d_out, int out_size) {
    const float* kin    = (const float*)d_in[0];
    const int*   cat    = (const int*)d_in[1];
    const float* scores = (const float*)d_in[2];
    float*       out    = (float*)d_out;

    (void)in_sizes; (void)n_in; (void)out_size;

    const int smem = 2 * TS * PITCH4 * (int)sizeof(float4);  // 66,560 B
    cudaFuncSetAttribute(k_pairs, cudaFuncAttributeMaxDynamicSharedMemorySize, smem);

    k_norm<<<NN / 8, 256>>>(kin, cat);
    k_build<<<1, 256>>>(cat);
    k_pairs<<<444, 256, smem>>>(kin);
    k_prep<<<NN / 256, 256>>>(out, cat, scores);
    k_finalize<<<NN / 4, 256>>>(out, kin);
}